// round 4
// baseline (speedup 1.0000x reference)
#include <cuda_runtime.h>
#include <math.h>

// Fixed shapes
#define BN 8192
#define DN 2048
#define TINV 10.0f           // 1/T, T = 0.1
#define NTHR 256             // 8 warps/block, 1 row/warp
#define WPB  (NTHR / 32)     // 8
#define NBLK (BN / WPB)      // 1024

// Scratch (device globals)
__device__ double g_partE[NBLK];
__device__ double g_partW[NBLK];
__device__ double g_partL[NBLK];
__device__ unsigned int g_count;

__device__ __forceinline__ float warp_sum(float v) {
    #pragma unroll
    for (int o = 16; o; o >>= 1) v += __shfl_xor_sync(0xffffffffu, v, o);
    return v;
}
__device__ __forceinline__ double warp_sum_d(double v) {
    #pragma unroll
    for (int o = 16; o; o >>= 1) v += __shfl_xor_sync(0xffffffffu, v, o);
    return v;
}

__global__ void __launch_bounds__(NTHR, 3)
fused_kernel(const float* __restrict__ embed,
             const float* __restrict__ ee,
             const float* __restrict__ labels,
             float* __restrict__ out) {
    __shared__ double  redE[WPB], redW[WPB], redL[WPB];
    __shared__ bool    s_last;

    const int tid  = threadIdx.x;
    const int warp = tid >> 5;
    const int lane = tid & 31;

    // ---- Pure streaming: one warp per row. NO pre-phase, NO syncs.
    //      Each warp computes dot(x,e0), ||x||^2, ||e0||^2 in one pass. ----
    const int row = blockIdx.x * WPB + warp;
    const float4* x4 = reinterpret_cast<const float4*>(ee + (size_t)row * DN);
    const float4* a4 = reinterpret_cast<const float4*>(embed);  // row 0

    float dot = 0.f, n2 = 0.f, na2 = 0.f;
    #pragma unroll
    for (int i = 0; i < DN / (4 * 32); i++) {        // 16 iterations
        float4 x = __ldcs(&x4[i * 32 + lane]);       // stream, evict-first
        float4 a = __ldg (&a4[i * 32 + lane]);       // L1-resident anchor
        dot = fmaf(x.x, a.x, dot);
        dot = fmaf(x.y, a.y, dot);
        dot = fmaf(x.z, a.z, dot);
        dot = fmaf(x.w, a.w, dot);
        n2  = fmaf(x.x, x.x, n2);
        n2  = fmaf(x.y, x.y, n2);
        n2  = fmaf(x.z, x.z, n2);
        n2  = fmaf(x.w, x.w, n2);
        na2 = fmaf(a.x, a.x, na2);
        na2 = fmaf(a.y, a.y, na2);
        na2 = fmaf(a.z, a.z, na2);
        na2 = fmaf(a.w, a.w, na2);
    }
    dot = warp_sum(dot);
    n2  = warp_sum(n2);
    na2 = warp_sum(na2);

    // ---- Per-warp epilogue ----
    if (lane == 0) {
        double E = 0.0, W = 0.0, L = 0.0;
        if (row != 0) {
            float norm0 = sqrtf(na2);
            float inv   = 1.0f / fmaxf(norm0, 1e-12f);     // F.normalize
            float na    = fmaxf(norm0 * inv, 1e-6f);       // cos eps on ||a_hat||
            float nb    = fmaxf(sqrtf(n2), 1e-6f);
            float neg   = -TINV * dot * inv / (na * nb);
            float lj    = labels[row];
            E = (double)expf(neg);
            W = (double)lj * (double)neg;
            L = (double)lj;
        }
        redE[warp] = E; redW[warp] = W; redL[warp] = L;
    }
    __syncthreads();

    // ---- Block partials -> scratch ----
    if (warp == 0) {
        double E = (lane < WPB) ? redE[lane] : 0.0;
        double W = (lane < WPB) ? redW[lane] : 0.0;
        double L = (lane < WPB) ? redL[lane] : 0.0;
        E = warp_sum_d(E); W = warp_sum_d(W); L = warp_sum_d(L);
        if (lane == 0) {
            g_partE[blockIdx.x] = E;
            g_partW[blockIdx.x] = W;
            g_partL[blockIdx.x] = L;
            __threadfence();
            unsigned int c = atomicAdd(&g_count, 1u);
            s_last = (c == NBLK - 1);
        }
    }
    __syncthreads();

    // ---- Last block reduces 1024 partials and finalizes ----
    if (s_last) {
        double E = 0.0, W = 0.0, L = 0.0;
        #pragma unroll
        for (int k = 0; k < NBLK / NTHR; k++) {       // 4 slots per thread
            int idx = k * NTHR + tid;
            E += g_partE[idx]; W += g_partW[idx]; L += g_partL[idx];
        }
        E = warp_sum_d(E); W = warp_sum_d(W); L = warp_sum_d(L);
        if (lane == 0) { redE[warp] = E; redW[warp] = W; redL[warp] = L; }
        __syncthreads();
        if (tid == 0) {
            double Et = 0, Wt = 0, Lt = 0;
            #pragma unroll
            for (int i = 0; i < WPB; i++) { Et += redE[i]; Wt += redW[i]; Lt += redL[i]; }
            double l0   = (double)labels[0];
            double E0   = 1e-12 + Et;
            double C0   = 1e-12 + l0 * Lt;
            double logE = log(E0);
            double L0   = (l0 / C0) * (logE * Lt - Wt);
            out[0] = (float)(L0 / (double)BN);
            g_count = 0;                               // reset for replay
        }
    }
}

extern "C" void kernel_launch(void* const* d_in, const int* in_sizes, int n_in,
                              void* d_out, int out_size) {
    const float* embed         = (const float*)d_in[0];
    const float* embed_enhance = (const float*)d_in[1];
    const float* labels        = (const float*)d_in[2];
    float* out = (float*)d_out;

    fused_kernel<<<NBLK, NTHR>>>(embed, embed_enhance, labels, out);
}

// round 6
// speedup vs baseline: 1.3582x; 1.3582x over previous
#include <cuda_runtime.h>
#include <math.h>

// Fixed shapes
#define BN 8192
#define DN 2048
#define TINV 10.0f            // 1/T, T = 0.1
#define NTHR 256              // 8 warps/block
#define WPB  (NTHR / 32)
#define NBLK 296              // 2 blocks per SM (148 SMs), warp-strided rows
#define TOTW (NBLK * WPB)     // 2368 warps

// Scratch (device globals)
__device__ double g_partE[NBLK];
__device__ double g_partW[NBLK];
__device__ double g_partL[NBLK];
__device__ unsigned int g_count;

__device__ __forceinline__ float warp_sum(float v) {
    #pragma unroll
    for (int o = 16; o; o >>= 1) v += __shfl_xor_sync(0xffffffffu, v, o);
    return v;
}
__device__ __forceinline__ double warp_sum_d(double v) {
    #pragma unroll
    for (int o = 16; o; o >>= 1) v += __shfl_xor_sync(0xffffffffu, v, o);
    return v;
}

__global__ void __launch_bounds__(NTHR, 2)
fused_kernel(const float* __restrict__ embed,
             const float* __restrict__ ee,
             const float* __restrict__ labels,
             float* __restrict__ out) {
    __shared__ double redE[WPB], redW[WPB], redL[WPB];
    __shared__ bool   s_last;

    const int tid  = threadIdx.x;
    const int warp = tid >> 5;
    const int lane = tid & 31;
    const int wg   = blockIdx.x * WPB + warp;   // global warp id

    // ---- Anchor: whole row 0 resident in registers (16 float4 per lane).
    //      Loaded once per warp; all warps hit the same 8 KB in L2/L1. ----
    const float4* a4 = reinterpret_cast<const float4*>(embed);
    float4 areg[16];
    float na2 = 0.f;
    #pragma unroll
    for (int i = 0; i < 16; i++) {
        float4 a = a4[i * 32 + lane];
        areg[i] = a;
        na2 = fmaf(a.x, a.x, na2);
        na2 = fmaf(a.y, a.y, na2);
        na2 = fmaf(a.z, a.z, na2);
        na2 = fmaf(a.w, a.w, na2);
    }
    na2 = warp_sum(na2);
    const float norm0 = sqrtf(na2);
    const float inv   = 1.0f / fmaxf(norm0, 1e-12f);          // F.normalize
    const float na    = fmaxf(norm0 * inv, 1e-6f);            // cos eps
    const float scale = TINV * inv / na;                      // neg = -scale*dot/nb

    // ---- Stream rows: x-loads are the ONLY memory traffic in the loop. ----
    double E = 0.0, W = 0.0, L = 0.0;
    for (int row = wg; row < BN; row += TOTW) {
        const float4* x4 = reinterpret_cast<const float4*>(ee + (size_t)row * DN);
        float dot = 0.f, n2 = 0.f;
        #pragma unroll
        for (int i = 0; i < 16; i++) {
            float4 x = x4[i * 32 + lane];
            float4 a = areg[i];
            dot = fmaf(x.x, a.x, dot);
            dot = fmaf(x.y, a.y, dot);
            dot = fmaf(x.z, a.z, dot);
            dot = fmaf(x.w, a.w, dot);
            n2  = fmaf(x.x, x.x, n2);
            n2  = fmaf(x.y, x.y, n2);
            n2  = fmaf(x.z, x.z, n2);
            n2  = fmaf(x.w, x.w, n2);
        }
        dot = warp_sum(dot);
        n2  = warp_sum(n2);
        if (lane == 0 && row != 0) {
            float nb  = fmaxf(sqrtf(n2), 1e-6f);
            float neg = -scale * dot / nb;
            float lj  = labels[row];
            E += (double)expf(neg);
            W += (double)lj * (double)neg;
            L += (double)lj;
        }
    }

    // ---- Block partials -> scratch ----
    if (lane == 0) { redE[warp] = E; redW[warp] = W; redL[warp] = L; }
    __syncthreads();
    if (warp == 0) {
        double e = (lane < WPB) ? redE[lane] : 0.0;
        double w = (lane < WPB) ? redW[lane] : 0.0;
        double l = (lane < WPB) ? redL[lane] : 0.0;
        e = warp_sum_d(e); w = warp_sum_d(w); l = warp_sum_d(l);
        if (lane == 0) {
            g_partE[blockIdx.x] = e;
            g_partW[blockIdx.x] = w;
            g_partL[blockIdx.x] = l;
            __threadfence();
            unsigned int c = atomicAdd(&g_count, 1u);
            s_last = (c == NBLK - 1);
        }
    }
    __syncthreads();

    // ---- Last block reduces ALL NBLK partials (strided: NBLK > NTHR!) ----
    if (s_last) {
        double e = 0.0, w = 0.0, l = 0.0;
        for (int idx = tid; idx < NBLK; idx += NTHR) {   // covers 256..295 too
            e += g_partE[idx]; w += g_partW[idx]; l += g_partL[idx];
        }
        e = warp_sum_d(e); w = warp_sum_d(w); l = warp_sum_d(l);
        if (lane == 0) { redE[warp] = e; redW[warp] = w; redL[warp] = l; }
        __syncthreads();
        if (tid == 0) {
            double Et = 0, Wt = 0, Lt = 0;
            #pragma unroll
            for (int i = 0; i < WPB; i++) { Et += redE[i]; Wt += redW[i]; Lt += redL[i]; }
            double l0   = (double)labels[0];
            double E0   = 1e-12 + Et;
            double C0   = 1e-12 + l0 * Lt;
            double logE = log(E0);
            double L0   = (l0 / C0) * (logE * Lt - Wt);
            out[0] = (float)(L0 / (double)BN);
            g_count = 0;                                  // reset for replay
        }
    }
}

extern "C" void kernel_launch(void* const* d_in, const int* in_sizes, int n_in,
                              void* d_out, int out_size) {
    const float* embed         = (const float*)d_in[0];
    const float* embed_enhance = (const float*)d_in[1];
    const float* labels        = (const float*)d_in[2];
    float* out = (float*)d_out;

    fused_kernel<<<NBLK, NTHR>>>(embed, embed_enhance, labels, out);
}